// round 2
// baseline (speedup 1.0000x reference)
#include <cuda_runtime.h>
#include <cstdint>

#define BATCH 4
#define C_IN 32
#define C_OUT 32
#define NNODE 163842
#define K7 7

#define TILE 512                 // nodes per block
#define NT ((NNODE + TILE - 1) / TILE)   // 321 tiles
#define PITCH 33                 // smem row pitch (odd -> conflict-free)
#define THREADS 128

// Transposed x scratch: [B, N, C_IN] (~84 MB). __device__ global (no cudaMalloc).
__device__ float g_xt[(size_t)BATCH * NNODE * C_IN];

// ---------------------------------------------------------------------------
// Kernel 1: transpose x [B, C_IN, N] -> xt [B, N, C_IN]
// ---------------------------------------------------------------------------
__global__ __launch_bounds__(256) void transpose_kernel(const float* __restrict__ x,
                                                        float* __restrict__ xt) {
    __shared__ float tile[32][33];
    const int b = blockIdx.y;
    const int n0 = blockIdx.x * 32;
    const int tx = threadIdx.x;
    const int ty = threadIdx.y;

    const int n_ld = n0 + tx;
#pragma unroll
    for (int c = ty; c < 32; c += 8) {
        float v = 0.0f;
        if (n_ld < NNODE) v = x[((size_t)b * C_IN + c) * NNODE + n_ld];
        tile[c][tx] = v;
    }
    __syncthreads();
#pragma unroll
    for (int r = ty; r < 32; r += 8) {
        const int n = n0 + r;
        if (n < NNODE) xt[((size_t)b * NNODE + n) * C_IN + tx] = tile[tx][r];
    }
}

// ---------------------------------------------------------------------------
// Helpers
// ---------------------------------------------------------------------------
__device__ __forceinline__ uint32_t s2u(const void* p) {
    uint32_t a;
    asm("{ .reg .u64 t; cvta.to.shared.u64 t, %1; cvt.u32.u64 %0, t; }"
        : "=r"(a) : "l"(p));
    return a;
}

#define CP_ASYNC4(daddr, src) \
    asm volatile("cp.async.ca.shared.global [%0], [%1], 4;" :: "r"(daddr), "l"(src))
#define CP_COMMIT() asm volatile("cp.async.commit_group;")
#define CP_WAIT(n)  asm volatile("cp.async.wait_group %0;" :: "n"(n))

// ---------------------------------------------------------------------------
// Kernel 2: tiled conv. Block = 128 threads, tile = 512 nodes for batch b.
// K=224 split into 7 chunks of 32 (one neighbor ring slot each), gathered
// warp-cooperatively via cp.async into double-buffered smem. Each thread
// computes 4 nodes x 32 outs with fma.rn.f32x2 (output pairs in lo/hi).
// ---------------------------------------------------------------------------
__global__ __launch_bounds__(THREADS, 1) void onering_conv_kernel(
    const float* __restrict__ xt,
    const float* __restrict__ W,      // [32][224]
    const float* __restrict__ bias,   // [32]
    const int* __restrict__ neigh,    // [N][7]
    float* __restrict__ out) {        // [B][32][N]

    extern __shared__ __align__(16) float smem[];
    float* As   = smem;                         // 2 * TILE * PITCH floats
    float* Wt   = As + 2 * TILE * PITCH;        // 224 * 32 (transposed W: [k][o])
    float* bs   = Wt + 224 * 32;                // 32
    int*   sidx = (int*)(bs + 32);              // TILE * 7

    const int tid  = threadIdx.x;
    const int wid  = tid >> 5;
    const int lane = tid & 31;
    const int b    = blockIdx.y;
    const int n0   = blockIdx.x * TILE;

    // Stage neighbor indices (coalesced; neigh rows are contiguous).
    for (int i = tid; i < TILE * K7; i += THREADS) {
        const int g = n0 * K7 + i;
        sidx[i] = (g < NNODE * K7) ? neigh[g] : 0;
    }
    // Build transposed W: Wt[k][o] = W[o][k]; pairs (o, o+1) contiguous.
    for (int i = tid; i < 224 * 32; i += THREADS) {
        const int k = i >> 5, o = i & 31;
        Wt[k * 32 + o] = W[o * 224 + k];
    }
    if (tid < 32) bs[tid] = bias[tid];
    __syncthreads();

    const float* xb = xt + (size_t)b * NNODE * C_IN;

    // Gather chunk j (neighbor slot j) into dst: dst[node][c] = xt[b][m][c].
    // Warp handles one node-row at a time: lane = channel -> 128B coalesced.
    auto gather = [&](float* dst, int j) {
#pragma unroll 4
        for (int r = wid; r < TILE; r += 4) {
            const int m = sidx[r * K7 + j];               // broadcast LDS
            const float* src = xb + (size_t)m * C_IN + lane;
            const uint32_t da = s2u(dst + r * PITCH + lane);
            CP_ASYNC4(da, src);
        }
    };

    // Accumulators: acc[i*16+p] holds f32x2 (out 2p, out 2p+1) for node i.
    uint64_t acc[64];
    {
        const uint64_t* b2 = (const uint64_t*)bs;
#pragma unroll
        for (int p = 0; p < 16; p++) {
            const uint64_t v = b2[p];
#pragma unroll
            for (int i = 0; i < 4; i++) acc[i * 16 + p] = v;
        }
    }

    // Prefetch chunk 0.
    gather(As, 0);
    CP_COMMIT();

#pragma unroll 1
    for (int j = 0; j < K7; j++) {
        if (j + 1 < K7) {
            gather(As + ((j + 1) & 1) * TILE * PITCH, j + 1);
            CP_COMMIT();
            CP_WAIT(1);     // chunk j complete (j+1 may still be in flight)
        } else {
            CP_WAIT(0);
        }
        __syncthreads();

        const float* A = As + (j & 1) * TILE * PITCH;
#pragma unroll 2
        for (int k = 0; k < 32; k++) {
            // a2[i] = (a, a) for this thread's 4 nodes at this k.
            uint64_t a2[4];
#pragma unroll
            for (int i = 0; i < 4; i++) {
                const float a = A[(tid + 128 * i) * PITCH + k];
                asm("mov.b64 %0, {%1, %1};" : "=l"(a2[i]) : "f"(a));
            }
            const uint64_t* wr = (const uint64_t*)(Wt + (j * 32 + k) * 32);
#pragma unroll
            for (int p = 0; p < 16; p++) {
                const uint64_t w2 = wr[p];   // broadcast LDS.64 (uniform addr)
#pragma unroll
                for (int i = 0; i < 4; i++) {
                    asm("fma.rn.f32x2 %0, %1, %2, %0;"
                        : "+l"(acc[i * 16 + p]) : "l"(a2[i]), "l"(w2));
                }
            }
        }
        __syncthreads();   // protect buffer before it is re-gathered
    }

    // Epilogue: out[b][o][n0 + tid + 128*i] — coalesced STG.32 per (i, o).
#pragma unroll
    for (int i = 0; i < 4; i++) {
        const int n = n0 + tid + 128 * i;
        if (n >= NNODE) continue;
        float* ob = out + (size_t)b * C_OUT * NNODE + n;
#pragma unroll
        for (int p = 0; p < 16; p++) {
            float lo, hi;
            asm("mov.b64 {%0, %1}, %2;" : "=f"(lo), "=f"(hi) : "l"(acc[i * 16 + p]));
            ob[(size_t)(2 * p) * NNODE]     = lo;
            ob[(size_t)(2 * p + 1) * NNODE] = hi;
        }
    }
}

// ---------------------------------------------------------------------------
// Launch
// ---------------------------------------------------------------------------
extern "C" void kernel_launch(void* const* d_in, const int* in_sizes, int n_in,
                              void* d_out, int out_size) {
    const float* x     = (const float*)d_in[0];
    const float* W     = (const float*)d_in[1];
    const float* bias  = (const float*)d_in[2];
    const int*   neigh = (const int*)d_in[3];
    float* out = (float*)d_out;

    float* xt = nullptr;
    cudaGetSymbolAddress((void**)&xt, g_xt);

    {
        dim3 block(32, 8);
        dim3 grid((NNODE + 31) / 32, BATCH);
        transpose_kernel<<<grid, block>>>(x, xt);
    }
    {
        const size_t shmem = (size_t)(2 * TILE * PITCH + 224 * 32 + 32) * 4
                           + (size_t)TILE * K7 * 4;   // = 178,304 B
        cudaFuncSetAttribute(onering_conv_kernel,
                             cudaFuncAttributeMaxDynamicSharedMemorySize,
                             (int)shmem);
        dim3 grid(NT, BATCH);
        onering_conv_kernel<<<grid, THREADS, shmem>>>(xt, W, bias, neigh, out);
    }
}

// round 3
// speedup vs baseline: 1.2708x; 1.2708x over previous
#include <cuda_runtime.h>
#include <cstdint>

#define BATCH 4
#define C_IN 32
#define C_OUT 32
#define NNODE 163842
#define K7 7

#define TILE 256
#define THREADS 256
#define PITCH 33
#define NT ((NNODE + TILE - 1) / TILE)   // 641

// Transposed x scratch: [B, N, C_IN] (~84 MB).
__device__ float g_xt[(size_t)BATCH * NNODE * C_IN];

// ---------------------------------------------------------------------------
// Kernel 1: transpose x [B, C_IN, N] -> xt [B, N, C_IN]
// ---------------------------------------------------------------------------
__global__ __launch_bounds__(256) void transpose_kernel(const float* __restrict__ x,
                                                        float* __restrict__ xt) {
    __shared__ float tile[32][33];
    const int b = blockIdx.y;
    const int n0 = blockIdx.x * 32;
    const int tx = threadIdx.x;
    const int ty = threadIdx.y;

    const int n_ld = n0 + tx;
#pragma unroll
    for (int c = ty; c < 32; c += 8) {
        float v = 0.0f;
        if (n_ld < NNODE) v = x[((size_t)b * C_IN + c) * NNODE + n_ld];
        tile[c][tx] = v;
    }
    __syncthreads();
#pragma unroll
    for (int r = ty; r < 32; r += 8) {
        const int n = n0 + r;
        if (n < NNODE) xt[((size_t)b * NNODE + n) * C_IN + tx] = tile[tx][r];
    }
}

// ---------------------------------------------------------------------------
// Helpers
// ---------------------------------------------------------------------------
__device__ __forceinline__ uint32_t s2u(const void* p) {
    uint32_t a;
    asm("{ .reg .u64 t; cvta.to.shared.u64 t, %1; cvt.u32.u64 %0, t; }"
        : "=r"(a) : "l"(p));
    return a;
}

#define CP_ASYNC4(daddr, src) \
    asm volatile("cp.async.ca.shared.global [%0], [%1], 4;" :: "r"(daddr), "l"(src))
#define CP_COMMIT() asm volatile("cp.async.commit_group;")
#define CP_WAIT(n)  asm volatile("cp.async.wait_group %0;" :: "n"(n))

// ---------------------------------------------------------------------------
// Kernel 2: tiled conv.
// Block = 256 threads = 2 output-groups x 128 threads; TILE = 256 nodes.
// Thread (g, t): nodes {n0+t, n0+t+128}, outputs [g*16, g*16+16) as 8 f32x2
// pairs. K=224 in 7 chunks of 32 (one ring slot), double-buffered cp.async
// gather (warp = one 128B neighbor row). 103.5 KB smem -> 2 blocks/SM.
// ---------------------------------------------------------------------------
__global__ __launch_bounds__(THREADS, 2) void onering_conv_kernel(
    const float* __restrict__ xt,
    const float* __restrict__ W,      // [32][224]
    const float* __restrict__ bias,   // [32]
    const int* __restrict__ neigh,    // [N][7]
    float* __restrict__ out) {        // [B][32][N]

    extern __shared__ __align__(16) float smem[];
    float* As   = smem;                          // 2 * TILE * PITCH = 16896 fl
    float* Wt   = As + 2 * TILE * PITCH;         // [k][o] transposed, 7168 fl
    float* bs   = Wt + 224 * 32;                 // 32 fl
    int*   sidx = (int*)(bs + 32);               // TILE*7 ints

    const int tid  = threadIdx.x;
    const int wid  = tid >> 5;
    const int lane = tid & 31;
    const int g    = tid >> 7;        // output group 0/1
    const int t    = tid & 127;       // thread within group
    const int b    = blockIdx.y;
    const int n0   = blockIdx.x * TILE;

    // Stage neighbor indices (coalesced).
#pragma unroll
    for (int i = tid; i < TILE * K7; i += THREADS) {
        const int gg = n0 * K7 + i;
        sidx[i] = (gg < NNODE * K7) ? neigh[gg] : 0;
    }
    // Transposed W: coalesced LDG, scattered STS (one-time).
#pragma unroll
    for (int i = tid; i < 224 * 32; i += THREADS) {
        const int o = i / 224, k = i % 224;
        Wt[k * 32 + o] = W[i];
    }
    if (tid < 32) bs[tid] = bias[tid];
    __syncthreads();

    const float* xb = xt + (size_t)b * NNODE * C_IN;

    // Warp-cooperative gather of ring slot j into dst (lane = channel).
    auto gather = [&](float* dst, int j) {
#pragma unroll
        for (int r = wid; r < TILE; r += 8) {
            const int m = sidx[r * K7 + j];
            const float* src = xb + (size_t)m * C_IN + lane;
            CP_ASYNC4(s2u(dst + r * PITCH + lane), src);
        }
    };

    // Accumulators: acc[i*8+p] = f32x2 (out g*16+2p, g*16+2p+1) for node i.
    uint64_t acc[16];
    {
        const uint64_t* b2 = (const uint64_t*)(bs + g * 16);
#pragma unroll
        for (int p = 0; p < 8; p++) {
            acc[p]     = b2[p];
            acc[8 + p] = b2[p];
        }
    }

    gather(As, 0);
    CP_COMMIT();

#pragma unroll 1
    for (int j = 0; j < K7; j++) {
        if (j + 1 < K7) {
            gather(As + ((j + 1) & 1) * TILE * PITCH, j + 1);
            CP_COMMIT();
            CP_WAIT(1);
        } else {
            CP_WAIT(0);
        }
        __syncthreads();

        const float* A = As + (j & 1) * TILE * PITCH;
        const float* Wj = Wt + j * 32 * 32 + g * 16;
#pragma unroll 8
        for (int k = 0; k < 32; k++) {
            const float a0 = A[t * PITCH + k];
            const float a1 = A[(t + 128) * PITCH + k];
            uint64_t a20, a21;
            asm("mov.b64 %0, {%1, %1};" : "=l"(a20) : "f"(a0));
            asm("mov.b64 %0, {%1, %1};" : "=l"(a21) : "f"(a1));
            const uint64_t* wr = (const uint64_t*)(Wj + k * 32);
#pragma unroll
            for (int p = 0; p < 8; p++) {
                const uint64_t w2 = wr[p];     // broadcast LDS.64
                asm("fma.rn.f32x2 %0, %1, %2, %0;" : "+l"(acc[p])     : "l"(a20), "l"(w2));
                asm("fma.rn.f32x2 %0, %1, %2, %0;" : "+l"(acc[8 + p]) : "l"(a21), "l"(w2));
            }
        }
        __syncthreads();
    }

    // Epilogue: out[b][o][n], coalesced STG.32 across t for each o.
#pragma unroll
    for (int i = 0; i < 2; i++) {
        const int n = n0 + t + 128 * i;
        if (n >= NNODE) continue;
        float* ob = out + (size_t)b * C_OUT * NNODE + (size_t)(g * 16) * NNODE + n;
#pragma unroll
        for (int p = 0; p < 8; p++) {
            float lo, hi;
            asm("mov.b64 {%0, %1}, %2;" : "=f"(lo), "=f"(hi) : "l"(acc[i * 8 + p]));
            ob[(size_t)(2 * p) * NNODE]     = lo;
            ob[(size_t)(2 * p + 1) * NNODE] = hi;
        }
    }
}

// ---------------------------------------------------------------------------
// Launch
// ---------------------------------------------------------------------------
extern "C" void kernel_launch(void* const* d_in, const int* in_sizes, int n_in,
                              void* d_out, int out_size) {
    const float* x     = (const float*)d_in[0];
    const float* W     = (const float*)d_in[1];
    const float* bias  = (const float*)d_in[2];
    const int*   neigh = (const int*)d_in[3];
    float* out = (float*)d_out;

    float* xt = nullptr;
    cudaGetSymbolAddress((void**)&xt, g_xt);

    {
        dim3 block(32, 8);
        dim3 grid((NNODE + 31) / 32, BATCH);
        transpose_kernel<<<grid, block>>>(x, xt);
    }
    {
        const size_t shmem = (size_t)(2 * TILE * PITCH + 224 * 32 + 32) * 4
                           + (size_t)TILE * K7 * 4;   // 103,552 B
        cudaFuncSetAttribute(onering_conv_kernel,
                             cudaFuncAttributeMaxDynamicSharedMemorySize,
                             (int)shmem);
        dim3 grid(NT, BATCH);
        onering_conv_kernel<<<grid, THREADS, shmem>>>(xt, W, bias, neigh, out);
    }
}

// round 4
// speedup vs baseline: 1.2785x; 1.0060x over previous
#include <cuda_runtime.h>
#include <cstdint>

#define BATCH 4
#define C_IN 32
#define C_OUT 32
#define NNODE 163842
#define K7 7

#define TILE 256
#define THREADS 256
#define PITCH 33
#define NT ((NNODE + TILE - 1) / TILE)   // 641

// Transposed x scratch: [B, N, C_IN] (~84 MB).
__device__ float g_xt[(size_t)BATCH * NNODE * C_IN];

// ---------------------------------------------------------------------------
// Kernel 1: transpose x [B, C_IN, N] -> xt [B, N, C_IN]
// ---------------------------------------------------------------------------
__global__ __launch_bounds__(256) void transpose_kernel(const float* __restrict__ x,
                                                        float* __restrict__ xt) {
    __shared__ float tile[32][33];
    const int b = blockIdx.y;
    const int n0 = blockIdx.x * 32;
    const int tx = threadIdx.x;
    const int ty = threadIdx.y;

    const int n_ld = n0 + tx;
#pragma unroll
    for (int c = ty; c < 32; c += 8) {
        float v = 0.0f;
        if (n_ld < NNODE) v = x[((size_t)b * C_IN + c) * NNODE + n_ld];
        tile[c][tx] = v;
    }
    __syncthreads();
#pragma unroll
    for (int r = ty; r < 32; r += 8) {
        const int n = n0 + r;
        if (n < NNODE) xt[((size_t)b * NNODE + n) * C_IN + tx] = tile[tx][r];
    }
}

// ---------------------------------------------------------------------------
// Helpers
// ---------------------------------------------------------------------------
__device__ __forceinline__ uint32_t s2u(const void* p) {
    uint32_t a;
    asm("{ .reg .u64 t; cvta.to.shared.u64 t, %1; cvt.u32.u64 %0, t; }"
        : "=r"(a) : "l"(p));
    return a;
}

#define CP_ASYNC4(daddr, src) \
    asm volatile("cp.async.ca.shared.global [%0], [%1], 4;" :: "r"(daddr), "l"(src))
#define CP_COMMIT() asm volatile("cp.async.commit_group;")
#define CP_WAIT(n)  asm volatile("cp.async.wait_group %0;" :: "n"(n))

// ---------------------------------------------------------------------------
// Kernel 2: tiled conv.
// Block = 256 threads = 2 output-groups x 128; TILE = 256 nodes. Thread
// (g, t): nodes {n0+t, n0+t+128}, outputs [g*16, g*16+16) as 8 f32x2 pairs.
// Weight reads are broadcast LDS.128 (ld.shared.v2.b64) -> 4 crossbar phases
// per warp-k instead of 8, pushing the kernel onto the fma pipe.
// ---------------------------------------------------------------------------
__global__ __launch_bounds__(THREADS, 2) void onering_conv_kernel(
    const float* __restrict__ xt,
    const float* __restrict__ W,      // [32][224]
    const float* __restrict__ bias,   // [32]
    const int* __restrict__ neigh,    // [N][7]
    float* __restrict__ out) {        // [B][32][N]

    extern __shared__ __align__(16) float smem[];
    float* As   = smem;                          // 2 * TILE * PITCH floats
    float* Wt   = As + 2 * TILE * PITCH;         // [k][o] transposed, 7168 fl
    float* bs   = Wt + 224 * 32;                 // 32 fl (64B-aligned)
    int*   sidx = (int*)(bs + 32);               // TILE*7 ints

    const int tid  = threadIdx.x;
    const int wid  = tid >> 5;
    const int lane = tid & 31;
    const int g    = tid >> 7;        // output group 0/1
    const int t    = tid & 127;       // thread within group
    const int b    = blockIdx.y;
    const int n0   = blockIdx.x * TILE;

    // Stage neighbor indices (coalesced).
#pragma unroll
    for (int i = tid; i < TILE * K7; i += THREADS) {
        const int gg = n0 * K7 + i;
        sidx[i] = (gg < NNODE * K7) ? neigh[gg] : 0;
    }
    // Transposed W: coalesced LDG, scattered STS (one-time).
#pragma unroll
    for (int i = tid; i < 224 * 32; i += THREADS) {
        const int o = i / 224, k = i % 224;
        Wt[k * 32 + o] = W[i];
    }
    if (tid < 32) bs[tid] = bias[tid];
    __syncthreads();

    const float* xb = xt + (size_t)b * NNODE * C_IN;

    // Warp-cooperative gather of ring slot j into dst (lane = channel).
    auto gather = [&](float* dst, int j) {
#pragma unroll
        for (int r = wid; r < TILE; r += 8) {
            const int m = sidx[r * K7 + j];
            const float* src = xb + (size_t)m * C_IN + lane;
            CP_ASYNC4(s2u(dst + r * PITCH + lane), src);
        }
    };

    // Accumulators: acc[i*8+p] = f32x2 (out g*16+2p, g*16+2p+1) for node i.
    uint64_t acc[16];
    {
        const uint64_t* b2 = (const uint64_t*)(bs + g * 16);
#pragma unroll
        for (int p = 0; p < 8; p++) {
            acc[p]     = b2[p];
            acc[8 + p] = b2[p];
        }
    }

    gather(As, 0);
    CP_COMMIT();

    // Shared-window base for this group's weight column (u32 byte address).
    const uint32_t wt_g = s2u(Wt + g * 16);
    const uint32_t as_u = s2u(As);

#pragma unroll 1
    for (int j = 0; j < K7; j++) {
        if (j + 1 < K7) {
            gather(As + ((j + 1) & 1) * TILE * PITCH, j + 1);
            CP_COMMIT();
            CP_WAIT(1);
        } else {
            CP_WAIT(0);
        }
        __syncthreads();

        const uint32_t a_base = as_u + ((j & 1) * TILE * PITCH) * 4;
        const uint32_t a0_u = a_base + (t * PITCH) * 4;
        const uint32_t a1_u = a_base + ((t + 128) * PITCH) * 4;
        const uint32_t w_j  = wt_g + (j * 32 * 32) * 4;

#pragma unroll 8
        for (int k = 0; k < 32; k++) {
            float a0, a1;
            asm("ld.shared.f32 %0, [%1];" : "=f"(a0) : "r"(a0_u + k * 4));
            asm("ld.shared.f32 %0, [%1];" : "=f"(a1) : "r"(a1_u + k * 4));
            uint64_t a20, a21;
            asm("mov.b64 %0, {%1, %1};" : "=l"(a20) : "f"(a0));
            asm("mov.b64 %0, {%1, %1};" : "=l"(a21) : "f"(a1));

            const uint32_t wk = w_j + k * 128;   // 32 floats per k row
#pragma unroll
            for (int q = 0; q < 2; q++) {
                uint64_t w01, w23, w45, w67;
                asm("ld.shared.v2.b64 {%0, %1}, [%2];"
                    : "=l"(w01), "=l"(w23) : "r"(wk + q * 32));
                asm("ld.shared.v2.b64 {%0, %1}, [%2];"
                    : "=l"(w45), "=l"(w67) : "r"(wk + q * 32 + 16));
                const int p0 = q * 4;
                asm("fma.rn.f32x2 %0, %1, %2, %0;" : "+l"(acc[p0 + 0]) : "l"(a20), "l"(w01));
                asm("fma.rn.f32x2 %0, %1, %2, %0;" : "+l"(acc[p0 + 1]) : "l"(a20), "l"(w23));
                asm("fma.rn.f32x2 %0, %1, %2, %0;" : "+l"(acc[p0 + 2]) : "l"(a20), "l"(w45));
                asm("fma.rn.f32x2 %0, %1, %2, %0;" : "+l"(acc[p0 + 3]) : "l"(a20), "l"(w67));
                asm("fma.rn.f32x2 %0, %1, %2, %0;" : "+l"(acc[8 + p0 + 0]) : "l"(a21), "l"(w01));
                asm("fma.rn.f32x2 %0, %1, %2, %0;" : "+l"(acc[8 + p0 + 1]) : "l"(a21), "l"(w23));
                asm("fma.rn.f32x2 %0, %1, %2, %0;" : "+l"(acc[8 + p0 + 2]) : "l"(a21), "l"(w45));
                asm("fma.rn.f32x2 %0, %1, %2, %0;" : "+l"(acc[8 + p0 + 3]) : "l"(a21), "l"(w67));
            }
        }
        __syncthreads();
    }

    // Epilogue: out[b][o][n], coalesced STG.32 across t for each o.
#pragma unroll
    for (int i = 0; i < 2; i++) {
        const int n = n0 + t + 128 * i;
        if (n >= NNODE) continue;
        float* ob = out + (size_t)b * C_OUT * NNODE + (size_t)(g * 16) * NNODE + n;
#pragma unroll
        for (int p = 0; p < 8; p++) {
            float lo, hi;
            asm("mov.b64 {%0, %1}, %2;" : "=f"(lo), "=f"(hi) : "l"(acc[i * 8 + p]));
            ob[(size_t)(2 * p) * NNODE]     = lo;
            ob[(size_t)(2 * p + 1) * NNODE] = hi;
        }
    }
}

// ---------------------------------------------------------------------------
// Launch
// ---------------------------------------------------------------------------
extern "C" void kernel_launch(void* const* d_in, const int* in_sizes, int n_in,
                              void* d_out, int out_size) {
    const float* x     = (const float*)d_in[0];
    const float* W     = (const float*)d_in[1];
    const float* bias  = (const float*)d_in[2];
    const int*   neigh = (const int*)d_in[3];
    float* out = (float*)d_out;

    float* xt = nullptr;
    cudaGetSymbolAddress((void**)&xt, g_xt);

    {
        dim3 block(32, 8);
        dim3 grid((NNODE + 31) / 32, BATCH);
        transpose_kernel<<<grid, block>>>(x, xt);
    }
    {
        const size_t shmem = (size_t)(2 * TILE * PITCH + 224 * 32 + 32) * 4
                           + (size_t)TILE * K7 * 4;   // 103,552 B
        cudaFuncSetAttribute(onering_conv_kernel,
                             cudaFuncAttributeMaxDynamicSharedMemorySize,
                             (int)shmem);
        dim3 grid(NT, BATCH);
        onering_conv_kernel<<<grid, THREADS, shmem>>>(xt, W, bias, neigh, out);
    }
}

// round 5
// speedup vs baseline: 1.4627x; 1.1441x over previous
#include <cuda_runtime.h>
#include <cstdint>

#define BATCH 4
#define C_IN 32
#define C_OUT 32
#define NNODE 163842
#define K7 7

#define TILE 512
#define THREADS 256
#define PITCH_A 17               // 16-k rows + 1 pad (odd -> conflict-free)
#define CHUNKS 14                // 7 ring slots x 2 half-rows of 16 ch
#define NT ((NNODE + TILE - 1) / TILE)   // 321

// Transposed x scratch: [B, N, C_IN] (~84 MB).
__device__ float g_xt[(size_t)BATCH * NNODE * C_IN];
// Staging for transposed weights + bias (copied into constant each launch).
__device__ float g_wt[224 * 32 + 32];
// Weights [k][o] + bias in constant memory: read via LDC port, NOT the smem crossbar.
__constant__ float cWb[224 * 32 + 32];

// ---------------------------------------------------------------------------
// Kernel 1: transpose x [B, C_IN, N] -> xt [B, N, C_IN]
// ---------------------------------------------------------------------------
__global__ __launch_bounds__(256) void transpose_kernel(const float* __restrict__ x,
                                                        float* __restrict__ xt) {
    __shared__ float tile[32][33];
    const int b = blockIdx.y;
    const int n0 = blockIdx.x * 32;
    const int tx = threadIdx.x;
    const int ty = threadIdx.y;

    const int n_ld = n0 + tx;
#pragma unroll
    for (int c = ty; c < 32; c += 8) {
        float v = 0.0f;
        if (n_ld < NNODE) v = x[((size_t)b * C_IN + c) * NNODE + n_ld];
        tile[c][tx] = v;
    }
    __syncthreads();
#pragma unroll
    for (int r = ty; r < 32; r += 8) {
        const int n = n0 + r;
        if (n < NNODE) xt[((size_t)b * NNODE + n) * C_IN + tx] = tile[tx][r];
    }
}

// Kernel 1b: transpose W [32][224] -> g_wt [224][32], append bias.
__global__ __launch_bounds__(256) void wt_transpose_kernel(const float* __restrict__ W,
                                                           const float* __restrict__ bias,
                                                           float* __restrict__ wt) {
    const int i = blockIdx.x * 256 + threadIdx.x;
    if (i < 224 * 32) {
        const int o = i / 224, k = i % 224;
        wt[k * 32 + o] = W[i];
    } else if (i < 224 * 32 + 32) {
        wt[i] = bias[i - 224 * 32];
    }
}

// ---------------------------------------------------------------------------
// Helpers
// ---------------------------------------------------------------------------
__device__ __forceinline__ uint32_t s2u(const void* p) {
    uint32_t a;
    asm("{ .reg .u64 t; cvta.to.shared.u64 t, %1; cvt.u32.u64 %0, t; }"
        : "=r"(a) : "l"(p));
    return a;
}

#define CP_ASYNC4(daddr, src) \
    asm volatile("cp.async.ca.shared.global [%0], [%1], 4;" :: "r"(daddr), "l"(src))
#define CP_COMMIT() asm volatile("cp.async.commit_group;")
#define CP_WAIT(n)  asm volatile("cp.async.wait_group %0;" :: "n"(n))

// ---------------------------------------------------------------------------
// Kernel 2: tiled conv.
// Block = 256 threads = 2 out-groups (g = tid>>7) x 128; TILE = 512 nodes.
// Thread (g, t): nodes {n0+t+128i, i<4}, outs [g*16, g*16+16) as 8 f32x2
// pairs. K=224 in 14 chunks of 16 (half a ring slot), double-buffered
// cp.async gather (half-warp = one 64B half-row). Weights from __constant__
// (LDC.128) so the smem crossbar carries only a-operands.
// ---------------------------------------------------------------------------
__global__ __launch_bounds__(THREADS, 2) void onering_conv_kernel(
    const float* __restrict__ xt,
    const int* __restrict__ neigh,    // [N][7]
    float* __restrict__ out) {        // [B][32][N]

    extern __shared__ __align__(16) float smem[];
    float* As   = smem;                          // 2 * TILE * PITCH_A floats
    int*   sidx = (int*)(As + 2 * TILE * PITCH_A);  // TILE*7 ints

    const int tid  = threadIdx.x;
    const int wid  = tid >> 5;
    const int lane = tid & 31;
    const int g    = tid >> 7;        // out group 0/1 (uniform per warp)
    const int t    = tid & 127;
    const int b    = blockIdx.y;
    const int n0   = blockIdx.x * TILE;

    // Stage neighbor indices (coalesced; clamp for the partial last tile).
#pragma unroll
    for (int i = tid; i < TILE * K7; i += THREADS) {
        const int gg = n0 * K7 + i;
        sidx[i] = (gg < NNODE * K7) ? neigh[gg] : 0;
    }
    __syncthreads();

    const float* xb = xt + (size_t)b * NNODE * C_IN;

    // Gather chunk c (= ring slot c>>1, half c&1) into dst.
    // Half-warp per 64B half-row: lane -> (row parity, channel).
    auto gather = [&](float* dst, int c) {
        const int j = c >> 1, h = c & 1;
        const int rsub = lane >> 4;          // 0/1: which of 2 rows
        const int ch   = lane & 15;          // channel within half
#pragma unroll
        for (int r0 = wid * 2; r0 < TILE; r0 += 16) {
            const int rp = r0 + rsub;
            const int m = sidx[rp * K7 + j];
            const float* src = xb + (size_t)m * C_IN + h * 16 + ch;
            CP_ASYNC4(s2u(dst + rp * PITCH_A + ch), src);
        }
    };

    // Accumulators: acc[i*8+p] = f32x2 (out g*16+2p, g*16+2p+1), node i.
    uint64_t acc[32];
    {
        const uint64_t* b2 = (const uint64_t*)(cWb + 224 * 32 + g * 16);
#pragma unroll
        for (int p = 0; p < 8; p++) {
            const uint64_t v = b2[p];
#pragma unroll
            for (int i = 0; i < 4; i++) acc[i * 8 + p] = v;
        }
    }

    gather(As, 0);
    CP_COMMIT();

#pragma unroll 1
    for (int c = 0; c < CHUNKS; c++) {
        if (c + 1 < CHUNKS) {
            gather(As + ((c + 1) & 1) * TILE * PITCH_A, c + 1);
            CP_COMMIT();
            CP_WAIT(1);
        } else {
            CP_WAIT(0);
        }
        __syncthreads();

        const float* A = As + (c & 1) * TILE * PITCH_A;
        const float* Wc = cWb + (c * 16) * 32 + g * 16;   // constant, [k][o]

#pragma unroll
        for (int kk = 0; kk < 16; kk++) {
            // 4 a-operands (one per node), splatted to f32x2.
            uint64_t a2[4];
#pragma unroll
            for (int i = 0; i < 4; i++) {
                const float a = A[(t + 128 * i) * PITCH_A + kk];
                asm("mov.b64 %0, {%1, %1};" : "=l"(a2[i]) : "f"(a));
            }
            // 16 weights for this k: 4 x LDC.128 from the constant port.
            const ulonglong2* wr =
                reinterpret_cast<const ulonglong2*>(Wc + kk * 32);
#pragma unroll
            for (int q = 0; q < 4; q++) {
                const ulonglong2 wv = wr[q];
                const int p0 = 2 * q;
#pragma unroll
                for (int i = 0; i < 4; i++) {
                    asm("fma.rn.f32x2 %0, %1, %2, %0;"
                        : "+l"(acc[i * 8 + p0])     : "l"(a2[i]), "l"(wv.x));
                    asm("fma.rn.f32x2 %0, %1, %2, %0;"
                        : "+l"(acc[i * 8 + p0 + 1]) : "l"(a2[i]), "l"(wv.y));
                }
            }
        }
        __syncthreads();
    }

    // Epilogue: out[b][o][n], coalesced STG.32 across t for each o.
#pragma unroll
    for (int i = 0; i < 4; i++) {
        const int n = n0 + t + 128 * i;
        if (n >= NNODE) continue;
        float* ob = out + (size_t)b * C_OUT * NNODE + (size_t)(g * 16) * NNODE + n;
#pragma unroll
        for (int p = 0; p < 8; p++) {
            float lo, hi;
            asm("mov.b64 {%0, %1}, %2;" : "=f"(lo), "=f"(hi) : "l"(acc[i * 8 + p]));
            ob[(size_t)(2 * p) * NNODE]     = lo;
            ob[(size_t)(2 * p + 1) * NNODE] = hi;
        }
    }
}

// ---------------------------------------------------------------------------
// Launch
// ---------------------------------------------------------------------------
extern "C" void kernel_launch(void* const* d_in, const int* in_sizes, int n_in,
                              void* d_out, int out_size) {
    const float* x     = (const float*)d_in[0];
    const float* W     = (const float*)d_in[1];
    const float* bias  = (const float*)d_in[2];
    const int*   neigh = (const int*)d_in[3];
    float* out = (float*)d_out;

    float* xt = nullptr;
    cudaGetSymbolAddress((void**)&xt, g_xt);
    float* wt = nullptr;
    cudaGetSymbolAddress((void**)&wt, g_wt);

    {
        dim3 block(32, 8);
        dim3 grid((NNODE + 31) / 32, BATCH);
        transpose_kernel<<<grid, block>>>(x, xt);
    }
    {
        wt_transpose_kernel<<<(224 * 32 + 32 + 255) / 256, 256>>>(W, bias, wt);
        // Install transposed weights+bias into constant memory (D2D, capturable).
        cudaMemcpyToSymbolAsync(cWb, wt, (224 * 32 + 32) * sizeof(float), 0,
                                cudaMemcpyDeviceToDevice, 0);
    }
    {
        const size_t shmem = (size_t)(2 * TILE * PITCH_A) * 4
                           + (size_t)TILE * K7 * 4;   // 69632 + 14336 = 83,968 B
        cudaFuncSetAttribute(onering_conv_kernel,
                             cudaFuncAttributeMaxDynamicSharedMemorySize,
                             (int)shmem);
        dim3 grid(NT, BATCH);
        onering_conv_kernel<<<grid, THREADS, shmem>>>(xt, neigh, out);
    }
}